// round 12
// baseline (speedup 1.0000x reference)
#include <cuda_runtime.h>
#include <math.h>

#define C        144
#define W        77
#define KW       10
#define FC       64
#define CONV_OUT 68                    // W - KW + 1
#define CONCAT   (C*FC + CONV_OUT)     // 9284
#define H2       128
#define GRID     (C + 1)               // 144 channel blocks + 1 conv block
#define NT       1024
#define PAD      64                    // 256 B accumulator stride (L2 slice spread)

// Scratch (no device allocation allowed); zeroed at load, reset by last block.
__device__ __align__(256) float g_hp[H2 * PAD];
__device__ unsigned int g_cnt = 0u;

__device__ __forceinline__ float warp_reduce(float v) {
#pragma unroll
    for (int o = 16; o > 0; o >>= 1) v += __shfl_down_sync(0xffffffffu, v, o);
    return v;
}

__device__ __forceinline__ float dot4(float4 a, float4 b) {
    return a.x * b.x + a.y * b.y + a.z * b.z + a.w * b.w;
}

// ---------------------------------------------------------------------------
// Barrier-minimal fused kernel.
//   Blocks 0..143 (channel c): front-batched FC (no barrier) + w2 column-
//     slice dot -> padded RED into g_hp.  (R8/R9 structure, best known.)
//   Block 144 (conv): runs CONCURRENTLY -- front-batches its w2 conv-column
//     registers, bulk-loads x (float4) into smem, computes conv[68], does the
//     128x68 conv matvec and REDs into g_hp. Removes all conv work from the
//     serial tail.
//   Last block (counter): tail = read g_hp + b2/w3/b3, relu/dot/sigmoid, STG.
//     One L2 round trip only. Resets scratch for next graph replay.
// ---------------------------------------------------------------------------
__global__ __launch_bounds__(NT, 1) void fused_kernel(
    const float* __restrict__ x,       // [C, W]
    const float* __restrict__ fc_w,    // [C, FC, W]
    const float* __restrict__ fc_b,    // [C, FC]
    const float* __restrict__ conv_w,  // [C, KW]
    const float* __restrict__ conv_b,  // [1]
    const float* __restrict__ w2,      // [H2, CONCAT]
    const float* __restrict__ b2,      // [H2]
    const float* __restrict__ w3,      // [1, H2]
    const float* __restrict__ b3,      // [1]
    float* __restrict__ out)           // [1]
{
    const int tid  = threadIdx.x;
    const int lane = tid & 31;
    const int warp = tid >> 5;
    const int b    = blockIdx.x;

    const int j = tid >> 3;            // 0..127 : w2 row owned by this thread
    const int p = tid & 7;             // 0..7   : position within row group

    __shared__ float xs2[C * W];       // conv block: all of x (44.4 KB)
    __shared__ __align__(16) float vals[FC];
    __shared__ __align__(16) float convv[CONV_OUT];
    __shared__ float sm_h[H2];
    __shared__ unsigned int s_last;

    if (b < C) {
        // ==================== channel block (c = b) =======================
        const int c = b;
        const bool tail = (lane < W - 64);               // 13-element tail

        // front-batched loads (max in-flight)
        const float4* wrow = reinterpret_cast<const float4*>(
            w2 + (size_t)j * CONCAT + c * FC);
        const float4 a0 = wrow[p];
        const float4 a1 = wrow[p + 8];

        const float* xr = x + c * W;
        const float x0 = xr[lane];
        const float x1 = xr[lane + 32];
        const float x2 = tail ? xr[lane + 64] : 0.f;

        const int d0 = warp * 2;
        const float* r0 = fc_w + (size_t)(c * FC + d0) * W;
        const float* r1 = r0 + W;
        const float f00 = r0[lane], f01 = r0[lane + 32], f02 = tail ? r0[lane + 64] : 0.f;
        const float f10 = r1[lane], f11 = r1[lane + 32], f12 = tail ? r1[lane + 64] : 0.f;
        const float bia0 = fc_b[c * FC + d0];
        const float bia1 = fc_b[c * FC + d0 + 1];

        // FC: no barrier needed before this
        float s0 = f00 * x0 + f01 * x1 + f02 * x2;
        float s1 = f10 * x0 + f11 * x1 + f12 * x2;
        s0 = warp_reduce(s0);
        s1 = warp_reduce(s1);
        if (lane == 0) {
            vals[d0]     = s0 + bia0;
            vals[d0 + 1] = s1 + bia1;
        }
        __syncthreads();               // vals visible

        // g_hp[j*PAD] += w2_slice[j,:] . vals
        const float4* v4 = reinterpret_cast<const float4*>(vals);
        float s = dot4(a0, v4[p]) + dot4(a1, v4[p + 8]);
#pragma unroll
        for (int o = 4; o > 0; o >>= 1)
            s += __shfl_down_sync(0xffffffffu, s, o, 8);
        if (p == 0) {
            atomicAdd(&g_hp[j * PAD], s);
            __threadfence();           // release my RED before my arrive
        }
    } else {
        // ========================= conv block =============================
        // front-batch w2 conv-column registers (independent of everything)
        const float4* crow = reinterpret_cast<const float4*>(
            w2 + (size_t)j * CONCAT + C * FC);           // 16B-aligned
        const float4 k0 = crow[p];
        const float4 k1 = crow[p + 8];
        float4 k2 = make_float4(0.f, 0.f, 0.f, 0.f);
        if (p == 0) k2 = crow[16];
        const float cb = conv_b[0];

        // bulk-load x into smem as float4 (11088 floats = 2772 float4)
        {
            const float4* x4 = reinterpret_cast<const float4*>(x);
            float4* xs4 = reinterpret_cast<float4*>(xs2);
#pragma unroll
            for (int k = 0; k < 2; k++) xs4[tid + k * NT] = x4[tid + k * NT];
            if (tid < 2772 - 2 * NT) xs4[2 * NT + tid] = x4[2 * NT + tid];
        }
        __syncthreads();

        // conv: warp w handles channels w, w+32, ..., lanes = output posns
        float c0 = 0.f, c1 = 0.f, c2 = 0.f;
        for (int ch = warp; ch < C; ch += 32) {
            const float* xrow = xs2 + ch * W;
            const float* cwp  = conv_w + ch * KW;
#pragma unroll
            for (int k = 0; k < KW; k++) {
                const float cv = __ldg(&cwp[k]);         // warp-uniform
                c0 += xrow[lane + k]      * cv;
                c1 += xrow[lane + 32 + k] * cv;
                if (lane < CONV_OUT - 64)
                    c2 += xrow[lane + 64 + k] * cv;
            }
        }
        if (tid < CONV_OUT) convv[tid] = 0.f;
        __syncthreads();
        atomicAdd(&convv[lane],      c0);                // smem atomics
        atomicAdd(&convv[lane + 32], c1);
        if (lane < CONV_OUT - 64) atomicAdd(&convv[lane + 64], c2);
        __syncthreads();
        if (tid < CONV_OUT) convv[tid] += cb;
        __syncthreads();

        // conv matvec: g_hp[j*PAD] += w2[j, 9216:9284] . convv
        const float4* cv4 = reinterpret_cast<const float4*>(convv);
        float s = dot4(k0, cv4[p]) + dot4(k1, cv4[p + 8]);
        if (p == 0) s += dot4(k2, cv4[16]);
#pragma unroll
        for (int o = 4; o > 0; o >>= 1)
            s += __shfl_down_sync(0xffffffffu, s, o, 8);
        if (p == 0) {
            atomicAdd(&g_hp[j * PAD], s);
            __threadfence();
        }
    }

    // ---- last-block election (no spinning; non-last blocks exit) --------
    __syncthreads();
    if (tid == 0)
        s_last = (atomicAdd(&g_cnt, 1u) == GRID - 1) ? 1u : 0u;
    __syncthreads();
    if (s_last == 0u) return;

    // ============== finalization (last block only; tiny tail) ============
    __threadfence();                   // acquire all g_hp updates

    if (tid < H2) {
        const float pre = g_hp[tid * PAD] + b2[tid];
        sm_h[tid] = fmaxf(pre, 0.f) * w3[tid];
        g_hp[tid * PAD] = 0.f;         // reset for next replay
    }
    __syncthreads();

    if (warp == 0) {
        float v = sm_h[lane] + sm_h[lane + 32]
                + sm_h[lane + 64] + sm_h[lane + 96];
        v = warp_reduce(v);
        if (lane == 0) {
            const float o2 = fmaxf(v + b3[0], 0.f);
            out[0] = 1.f / (1.f + __expf(-o2));
            g_cnt  = 0u;               // reset for next replay
        }
    }
}

// ---------------------------------------------------------------------------
extern "C" void kernel_launch(void* const* d_in, const int* in_sizes, int n_in,
                              void* d_out, int out_size) {
    const float* x      = (const float*)d_in[0];
    const float* fc_w   = (const float*)d_in[1];
    const float* fc_b   = (const float*)d_in[2];
    const float* conv_w = (const float*)d_in[3];
    const float* conv_b = (const float*)d_in[4];
    const float* w2     = (const float*)d_in[5];
    const float* b2     = (const float*)d_in[6];
    const float* w3     = (const float*)d_in[7];
    const float* b3     = (const float*)d_in[8];

    fused_kernel<<<GRID, NT>>>(x, fc_w, fc_b, conv_w, conv_b,
                               w2, b2, w3, b3, (float*)d_out);
}

// round 14
// speedup vs baseline: 1.0226x; 1.0226x over previous
#include <cuda_runtime.h>
#include <math.h>

#define C        144
#define W        77
#define KW       10
#define FC       64
#define CONV_OUT 68                    // W - KW + 1
#define CONCAT   (C*FC + CONV_OUT)     // 9284
#define H2       128
#define GRID     (C + 1)               // 144 channel blocks + 1 matvec block
#define NT       1024
#define PAD      64                    // 256 B accumulator stride (L2 slice spread)

// Scratch (no device allocation allowed); zeroed at load, reset by last block.
__device__ __align__(256) float g_hp[H2 * PAD];
__device__ __align__(256) float g_convp[CONV_OUT * PAD];
__device__ unsigned int g_cnt  = 0u;   // main completion counter
__device__ unsigned int g_ccnt = 0u;   // conv-contribution counter

__device__ __forceinline__ float warp_reduce(float v) {
#pragma unroll
    for (int o = 16; o > 0; o >>= 1) v += __shfl_down_sync(0xffffffffu, v, o);
    return v;
}

__device__ __forceinline__ float group8_reduce(float v) {
#pragma unroll
    for (int o = 4; o > 0; o >>= 1)
        v += __shfl_down_sync(0xffffffffu, v, o, 8);
    return v;
}

__device__ __forceinline__ float dot4(float4 a, float4 b) {
    return a.x * b.x + a.y * b.y + a.z * b.z + a.w * b.w;
}

// ---------------------------------------------------------------------------
// Blocks 0..143 (channel c):
//   front-batch w2 slice + x + fc_w -> conv REDs (direct x loads) -> FC
//   (shfl reduce) -> vals -> bar -> tid0 arrives conv counter -> w2 dot ->
//   padded RED into g_hp.
// Block 144 (conv matvec): front-batches w2 conv columns into registers at
//   entry (overlaps all other blocks), waits on conv counter, then matvec
//   g_hp[j] += w2[j,9216:9284] . (g_convp + conv_b). No conv work in tail.
// Last block on main counter: tiny tail = g_hp -> relu -> w3 dot -> sigmoid.
// ---------------------------------------------------------------------------
__global__ __launch_bounds__(NT, 1) void fused_kernel(
    const float* __restrict__ x,       // [C, W]
    const float* __restrict__ fc_w,    // [C, FC, W]
    const float* __restrict__ fc_b,    // [C, FC]
    const float* __restrict__ conv_w,  // [C, KW]
    const float* __restrict__ conv_b,  // [1]
    const float* __restrict__ w2,      // [H2, CONCAT]
    const float* __restrict__ b2,      // [H2]
    const float* __restrict__ w3,      // [1, H2]
    const float* __restrict__ b3,      // [1]
    float* __restrict__ out)           // [1]
{
    const int tid  = threadIdx.x;
    const int lane = tid & 31;
    const int warp = tid >> 5;
    const int b    = blockIdx.x;

    const int j = tid >> 3;            // 0..127 : w2 row owned by this thread
    const int p = tid & 7;             // 0..7   : position within row group

    __shared__ __align__(16) float vals[FC];
    __shared__ __align__(16) float convv[CONV_OUT];
    __shared__ float sm_h[H2];
    __shared__ unsigned int s_last;

    if (b < C) {
        // ==================== channel block (c = b) =======================
        const int c = b;
        const bool tail = (lane < W - 64);           // 13-element tail

        // ---- front-batched loads ----
        const float4* wrow = reinterpret_cast<const float4*>(
            w2 + (size_t)j * CONCAT + c * FC);
        const float4 a0 = wrow[p];
        const float4 a1 = wrow[p + 8];

        const float* xr = x + c * W;
        const float x0 = xr[lane];
        const float x1 = xr[lane + 32];
        const float x2 = tail ? xr[lane + 64] : 0.f;

        const int d0 = warp * 2;
        const float* r0 = fc_w + (size_t)(c * FC + d0) * W;
        const float* r1 = r0 + W;
        const float f00 = r0[lane], f01 = r0[lane + 32], f02 = tail ? r0[lane + 64] : 0.f;
        const float f10 = r1[lane], f11 = r1[lane + 32], f12 = tail ? r1[lane + 64] : 0.f;
        const float bia0 = fc_b[c * FC + d0];
        const float bia1 = fc_b[c * FC + d0 + 1];

        // ---- conv contribution: direct x loads (L1-hit), RED, fence ----
        if (tid < CONV_OUT) {
            float s = 0.f;
#pragma unroll
            for (int k = 0; k < KW; k++)
                s += xr[tid + k] * __ldg(&conv_w[c * KW + k]);
            atomicAdd(&g_convp[tid * PAD], s);
            __threadfence();           // release my conv RED
        }

        // ---- FC: 32 warps x 2 outputs, shfl warp reduce ----
        {
            float s0 = f00 * x0 + f01 * x1 + f02 * x2;
            float s1 = f10 * x0 + f11 * x1 + f12 * x2;
            s0 = warp_reduce(s0);
            s1 = warp_reduce(s1);
            if (lane == 0) {
                vals[d0]     = s0 + bia0;
                vals[d0 + 1] = s1 + bia1;
            }
        }
        __syncthreads();               // vals visible; conv REDs fenced

        // ---- unblock the matvec block ASAP (hidden behind w2 dot) ----
        if (tid == 0) atomicAdd(&g_ccnt, 1u);

        // ---- g_hp[j*PAD] += w2_slice[j,:] . vals ----
        {
            const float4* v4 = reinterpret_cast<const float4*>(vals);
            float s = dot4(a0, v4[p]) + dot4(a1, v4[p + 8]);
            s = group8_reduce(s);
            if (p == 0) {
                atomicAdd(&g_hp[j * PAD], s);
                __threadfence();       // release my h RED
            }
        }
    } else {
        // =================== conv matvec block (b == 144) =================
        // front-batch w2 conv-column registers (overlaps everyone's work)
        const float4* crow = reinterpret_cast<const float4*>(
            w2 + (size_t)j * CONCAT + C * FC);           // 16B-aligned
        const float4 k0 = crow[p];
        const float4 k1 = crow[p + 8];
        float4 k2 = make_float4(0.f, 0.f, 0.f, 0.f);
        if (p == 0) k2 = crow[16];
        const float cb = conv_b[0];

        // wait until all 144 channel blocks delivered their conv REDs
        if (tid == 0) {
            while (atomicAdd(&g_ccnt, 0u) < C) { __nanosleep(64); }
        }
        __syncthreads();
        __threadfence();               // acquire conv REDs

        if (tid < CONV_OUT)
            convv[tid] = g_convp[tid * PAD] + cb;
        __syncthreads();

        // g_hp[j*PAD] += w2[j, 9216:9284] . convv
        {
            const float4* cv4 = reinterpret_cast<const float4*>(convv);
            float s = dot4(k0, cv4[p]) + dot4(k1, cv4[p + 8]);
            if (p == 0) s += dot4(k2, cv4[16]);
            s = group8_reduce(s);
            if (p == 0) {
                atomicAdd(&g_hp[j * PAD], s);
                __threadfence();
            }
        }
    }

    // ---- last-block election (no spinning; non-last blocks exit) --------
    __syncthreads();
    if (tid == 0)
        s_last = (atomicAdd(&g_cnt, 1u) == GRID - 1) ? 1u : 0u;
    __syncthreads();
    if (s_last == 0u) return;

    // ============== finalization (last block only; tiny tail) ============
    __threadfence();                   // acquire all g_hp updates

    if (tid < H2) {
        const float pre = g_hp[tid * PAD] + b2[tid];
        sm_h[tid] = fmaxf(pre, 0.f) * w3[tid];
        g_hp[tid * PAD] = 0.f;         // reset for next replay
    }
    if (tid < CONV_OUT) g_convp[tid * PAD] = 0.f;        // reset
    __syncthreads();

    if (warp == 0) {
        float v = sm_h[lane] + sm_h[lane + 32]
                + sm_h[lane + 64] + sm_h[lane + 96];
        v = warp_reduce(v);
        if (lane == 0) {
            const float o2 = fmaxf(v + b3[0], 0.f);
            out[0] = 1.f / (1.f + __expf(-o2));
            g_cnt  = 0u;               // reset for next replay
            g_ccnt = 0u;
        }
    }
}

// ---------------------------------------------------------------------------
extern "C" void kernel_launch(void* const* d_in, const int* in_sizes, int n_in,
                              void* d_out, int out_size) {
    const float* x      = (const float*)d_in[0];
    const float* fc_w   = (const float*)d_in[1];
    const float* fc_b   = (const float*)d_in[2];
    const float* conv_w = (const float*)d_in[3];
    const float* conv_b = (const float*)d_in[4];
    const float* w2     = (const float*)d_in[5];
    const float* b2     = (const float*)d_in[6];
    const float* w3     = (const float*)d_in[7];
    const float* b3     = (const float*)d_in[8];

    fused_kernel<<<GRID, NT>>>(x, fc_w, fc_b, conv_w, conv_b,
                               w2, b2, w3, b3, (float*)d_out);
}

// round 15
// speedup vs baseline: 1.2216x; 1.1946x over previous
#include <cuda_runtime.h>
#include <math.h>

#define C        144
#define W        77
#define KW       10
#define FC       64
#define CONV_OUT 68                    // W - KW + 1
#define CONCAT   (C*FC + CONV_OUT)     // 9284
#define H2       128
#define GRID     C                     // one block per channel
#define NT       1024
#define PAD      64                    // 256 B accumulator stride (L2 slice spread)

// Scratch (no device allocation allowed); zeroed at load, reset by last block.
__device__ __align__(256) float g_hp[H2 * PAD];
__device__ __align__(256) float g_convp[CONV_OUT * PAD];
__device__ unsigned int g_cnt = 0u;

__device__ __forceinline__ float warp_reduce(float v) {
#pragma unroll
    for (int o = 16; o > 0; o >>= 1) v += __shfl_down_sync(0xffffffffu, v, o);
    return v;
}

__device__ __forceinline__ float group8_reduce(float v) {
#pragma unroll
    for (int o = 4; o > 0; o >>= 1)
        v += __shfl_down_sync(0xffffffffu, v, o, 8);
    return v;
}

__device__ __forceinline__ float dot4(float4 a, float4 b) {
    return a.x * b.x + a.y * b.y + a.z * b.z + a.w * b.w;
}

// release-scoped float RED: fuses the memory fence into the atomic (no MEMBAR)
__device__ __forceinline__ void red_release_add(float* addr, float v) {
    asm volatile("red.release.gpu.global.add.f32 [%0], %1;"
                 :: "l"(addr), "f"(v) : "memory");
}

// acq_rel counter: last block's acquire orders all prior release-REDs
__device__ __forceinline__ unsigned atom_acqrel_inc(unsigned int* addr) {
    unsigned r;
    asm volatile("atom.acq_rel.gpu.global.add.u32 %0, [%1], 1;"
                 : "=r"(r) : "l"(addr) : "memory");
    return r;
}

// ---------------------------------------------------------------------------
// R9 structure + fence-free atomics + single-round-trip tail.
//   Block c: front-batched loads -> FC (no barrier) -> one __syncthreads ->
//            conv RED (release) + w2-slice dot -> g_hp RED (release).
//   Last block (acq_rel counter): front-batches w2-conv regs, g_convp
//            scalars, g_hp, b2, w3 in ONE independent load wave, then
//            computes conv matvec + relu/w3/sigmoid and resets scratch.
// ---------------------------------------------------------------------------
__global__ __launch_bounds__(NT, 1) void fused_kernel(
    const float* __restrict__ x,       // [C, W]
    const float* __restrict__ fc_w,    // [C, FC, W]
    const float* __restrict__ fc_b,    // [C, FC]
    const float* __restrict__ conv_w,  // [C, KW]
    const float* __restrict__ conv_b,  // [1]
    const float* __restrict__ w2,      // [H2, CONCAT]
    const float* __restrict__ b2,      // [H2]
    const float* __restrict__ w3,      // [1, H2]
    const float* __restrict__ b3,      // [1]
    float* __restrict__ out)           // [1]
{
    const int tid  = threadIdx.x;
    const int lane = tid & 31;
    const int warp = tid >> 5;
    const int c    = blockIdx.x;

    const int j = tid >> 3;            // 0..127 : w2 row owned by this thread
    const int p = tid & 7;             // 0..7   : position within row group

    __shared__ float xs[W];
    __shared__ float cw[KW];
    __shared__ __align__(16) float vals[FC];
    __shared__ float sm_h[H2];
    __shared__ unsigned int s_last;

    // =============== front-batched global loads (max MLP) ===============
    const bool tail = (lane < W - 64);                   // 13-element tail

    // (1) w2 FC slice: row j cols [c*64, +64) = 16 float4; 8 th/row, 2 each
    const float4* wrow = reinterpret_cast<const float4*>(
        w2 + (size_t)j * CONCAT + c * FC);
    const float4 a0 = wrow[p];
    const float4 a1 = wrow[p + 8];

    // (2) per-warp x slice (redundant across warps; tiny + L2-hot)
    const float* xr = x + c * W;
    const float x0 = xr[lane];
    const float x1 = xr[lane + 32];
    const float x2 = tail ? xr[lane + 64] : 0.f;

    // (3) fc_w operands for this warp's 2 outputs
    const int d0 = warp * 2;
    const float* r0 = fc_w + (size_t)(c * FC + d0) * W;
    const float* r1 = r0 + W;
    const float f00 = r0[lane], f01 = r0[lane + 32], f02 = tail ? r0[lane + 64] : 0.f;
    const float f10 = r1[lane], f11 = r1[lane + 32], f12 = tail ? r1[lane + 64] : 0.f;

    // (4) xs / conv weights into smem (consumed after the single barrier)
    if (tid < W)               xs[tid]     = xr[tid];
    else if (tid < W + KW)     cw[tid - W] = conv_w[c * KW + (tid - W)];

    // =================== FC: no barrier needed ===========================
    {
        float s0 = f00 * x0 + f01 * x1 + f02 * x2;
        float s1 = f10 * x0 + f11 * x1 + f12 * x2;
        s0 = warp_reduce(s0);
        s1 = warp_reduce(s1);
        if (lane == 0) {
            vals[d0]     = s0 + fc_b[c * FC + d0];
            vals[d0 + 1] = s1 + fc_b[c * FC + d0 + 1];
        }
    }

    __syncthreads();                   // vals[] and xs[]/cw[] now visible

    // ---------------- conv contribution (release RED) --------------------
    if (tid < CONV_OUT) {
        float s = 0.f;
#pragma unroll
        for (int k = 0; k < KW; k++) s += xs[tid + k] * cw[k];
        red_release_add(&g_convp[tid * PAD], s);
    }

    // -------------- g_hp[j*PAD] += w2_slice[j,:] . vals ------------------
    {
        const float4* v4 = reinterpret_cast<const float4*>(vals);
        float s = dot4(a0, v4[p]) + dot4(a1, v4[p + 8]);
        s = group8_reduce(s);
        if (p == 0) red_release_add(&g_hp[j * PAD], s);
    }

    // ---- last-block election (no spinning; non-last blocks exit) --------
    __syncthreads();
    if (tid == 0)
        s_last = (atom_acqrel_inc(&g_cnt) == GRID - 1) ? 1u : 0u;
    __syncthreads();
    if (s_last == 0u) return;

    // ====== finalization (last block only; ONE independent load wave) ====
    // all loads below are independent of each other -> single round trip
    const float4* rw = reinterpret_cast<const float4*>(
        w2 + (size_t)j * CONCAT + C * FC);               // 16B-aligned
    const float4 rk0 = rw[p];
    const float4 rk1 = rw[p + 8];
    float4 rk2 = make_float4(0.f, 0.f, 0.f, 0.f);
    if (p == 0) rk2 = rw[16];

    const float cb = conv_b[0];
    // this thread's conv values, loaded directly from padded scratch
    float cv0[4], cv1[4], cv2[4];
#pragma unroll
    for (int i = 0; i < 4; i++) {
        cv0[i] = g_convp[(p * 4 + i) * PAD] + cb;
        cv1[i] = g_convp[(32 + p * 4 + i) * PAD] + cb;
    }
#pragma unroll
    for (int i = 0; i < 4; i++)
        cv2[i] = (p == 0) ? g_convp[(64 + i) * PAD] + cb : 0.f;

    const float hacc = (p == 0) ? g_hp[j * PAD] : 0.f;
    const float bj   = (p == 0) ? b2[j] : 0.f;
    const float wj   = (p == 0) ? w3[j] : 0.f;

    // conv matvec + activation
    {
        float s = rk0.x * cv0[0] + rk0.y * cv0[1] + rk0.z * cv0[2] + rk0.w * cv0[3]
                + rk1.x * cv1[0] + rk1.y * cv1[1] + rk1.z * cv1[2] + rk1.w * cv1[3];
        if (p == 0)
            s += rk2.x * cv2[0] + rk2.y * cv2[1] + rk2.z * cv2[2] + rk2.w * cv2[3];
        s = group8_reduce(s);
        if (p == 0) {
            sm_h[j] = fmaxf(hacc + s + bj, 0.f) * wj;
            g_hp[j * PAD] = 0.f;       // reset for next replay
        }
    }
    if (tid < CONV_OUT) g_convp[tid * PAD] = 0.f;        // reset
    __syncthreads();

    if (warp == 0) {
        float v = sm_h[lane] + sm_h[lane + 32]
                + sm_h[lane + 64] + sm_h[lane + 96];
        v = warp_reduce(v);
        if (lane == 0) {
            const float o2 = fmaxf(v + b3[0], 0.f);
            out[0] = 1.f / (1.f + __expf(-o2));
            g_cnt = 0u;                // reset for next replay
        }
    }
}

// ---------------------------------------------------------------------------
extern "C" void kernel_launch(void* const* d_in, const int* in_sizes, int n_in,
                              void* d_out, int out_size) {
    const float* x      = (const float*)d_in[0];
    const float* fc_w   = (const float*)d_in[1];
    const float* fc_b   = (const float*)d_in[2];
    const float* conv_w = (const float*)d_in[3];
    const float* conv_b = (const float*)d_in[4];
    const float* w2     = (const float*)d_in[5];
    const float* b2     = (const float*)d_in[6];
    const float* w3     = (const float*)d_in[7];
    const float* b3     = (const float*)d_in[8];

    fused_kernel<<<GRID, NT>>>(x, fc_w, fc_b, conv_w, conv_b,
                               w2, b2, w3, b3, (float*)d_out);
}